// round 12
// baseline (speedup 1.0000x reference)
#include <cuda_runtime.h>

#define MULc 16
#define S0c 8
#define S1c 8
#define SOUTc 8
#define P3c 8
#define P4c 4
#define NPATH (P3c + P4c)

#define EPB 8
#define NTHREADS 32
#define WS 196                          // == 4 (mod 32)

__device__ __forceinline__ float4 f4fma(float s, float4 v, float4 a) {
    a.x = fmaf(s, v.x, a.x);
    a.y = fmaf(s, v.y, a.y);
    a.z = fmaf(s, v.z, a.z);
    a.w = fmaf(s, v.w, a.w);
    return a;
}

__global__ __launch_bounds__(NTHREADS) void tp_kernel(
    const float* __restrict__ x0, const int* __restrict__ i0,
    const float* __restrict__ x1, const float* __restrict__ C3,
    const float* __restrict__ C4, const int* __restrict__ p3,
    const int* __restrict__ p4, float* __restrict__ out, int E)
{
    __shared__ __align__(16) float  sW[EPB * WS];     // 6272 B
    __shared__ __align__(16) float4 sx1[EPB * S1c];   // 1024 B

    const int tid  = threadIdx.x;
    const int base = blockIdx.x * EPB;
    int nE = E - base; if (nE > EPB) nE = EPB;

    // ---- stage x1 rows (8 edges x 8 float4 = 64; 2 per lane) ----
    {
        const float4* src = reinterpret_cast<const float4*>(x1 + (size_t)base * 32);
        const int lim = nE * 8;
        for (int t = tid; t < lim; t += NTHREADS) sx1[t] = src[t];
    }
    __syncwarp();

    // ---- W build (identical structure to R8: C in regs, amortized over 8 edges) ----
    {
        const int g  = (tid >> 4) & 1;     // half-warp
        const int l  = tid & 15;           // (i,k)
        const int wi = l >> 2, wk = l & 3;

        // 3-paths: 4 passes, half-warps handle p = 2*pass + g
        #pragma unroll
        for (int pass = 0; pass < 4; pass++) {
            const int p = pass * 2 + g;
            const int segb = __ldg(&p3[p * 3 + 1]);
            const float c0  = __ldg(&C3[p * 64 + wi * 16 + 0  + wk]);
            const float c1  = __ldg(&C3[p * 64 + wi * 16 + 4  + wk]);
            const float c2  = __ldg(&C3[p * 64 + wi * 16 + 8  + wk]);
            const float c3v = __ldg(&C3[p * 64 + wi * 16 + 12 + wk]);
            for (int e = 0; e < nE; e++) {
                const float4 b = sx1[e * S1c + segb];
                sW[e * WS + p * 16 + l] =
                    fmaf(b.x, c0, fmaf(b.y, c1, fmaf(b.z, c2, b.w * c3v)));
            }
        }
        // 4-paths: 2 passes, half-warps handle q = 2*pass + g
        #pragma unroll
        for (int pass = 0; pass < 2; pass++) {
            const int q = pass * 2 + g;
            const int segb = __ldg(&p4[q * 4 + 1]);
            const int segc = __ldg(&p4[q * 4 + 2]);
            float creg[16];
            #pragma unroll
            for (int j = 0; j < 4; j++)
                #pragma unroll
                for (int m = 0; m < 4; m++)
                    creg[j * 4 + m] = __ldg(&C4[q * 256 + wi * 64 + j * 16 + m * 4 + wk]);
            for (int e = 0; e < nE; e++) {
                const float4 b = sx1[e * S1c + segb];
                const float4 c = sx1[e * S1c + segc];
                float t0 = fmaf(c.x, creg[0],  fmaf(c.y, creg[1],  fmaf(c.z, creg[2],  c.w * creg[3])));
                float t1 = fmaf(c.x, creg[4],  fmaf(c.y, creg[5],  fmaf(c.z, creg[6],  c.w * creg[7])));
                float t2 = fmaf(c.x, creg[8],  fmaf(c.y, creg[9],  fmaf(c.z, creg[10], c.w * creg[11])));
                float t3 = fmaf(c.x, creg[12], fmaf(c.y, creg[13], fmaf(c.z, creg[14], c.w * creg[15])));
                sW[e * WS + (P3c + q) * 16 + l] =
                    fmaf(b.x, t0, fmaf(b.y, t1, fmaf(b.z, t2, b.w * t3)));
            }
        }
    }
    __syncwarp();

    // ---- contrib: 16 lanes per edge, loop over 4 edge-pairs ----
    const int eL = tid >> 4;       // 0 or 1 within pair
    const int u  = tid & 15;       // mul index

    // packed metadata: s | (z << 16)  (loaded once per warp)
    int m3[P3c], m4[P4c];
    #pragma unroll
    for (int p = 0; p < P3c; p++)
        m3[p] = __ldg(&p3[p * 3 + 0]) | (__ldg(&p3[p * 3 + 2]) << 16);
    #pragma unroll
    for (int p = 0; p < P4c; p++)
        m4[p] = __ldg(&p4[p * 4 + 0]) | (__ldg(&p4[p * 4 + 3]) << 16);

    #pragma unroll
    for (int ep = 0; ep < EPB / 2; ep++) {
        const int eloc = ep * 2 + eL;
        const int e = base + eloc;
        if (e >= E) break;

        const float4* arow = reinterpret_cast<const float4*>(
            x0 + (size_t)__ldg(&i0[e]) * (S0c * MULc * 4));
        float4* orow = reinterpret_cast<float4*>(out + (size_t)e * (SOUTc * MULc * 4));
        const float* wbase = sW + eloc * WS;

        #pragma unroll
        for (int z = 0; z < SOUTc; z++) {
            float4 acc = make_float4(0.f, 0.f, 0.f, 0.f);
            #pragma unroll
            for (int pp = 0; pp < NPATH; pp++) {
                const int meta = (pp < P3c) ? m3[pp] : m4[pp - P3c];
                if ((meta >> 16) == z) {
                    const int sp = meta & 0xffff;
                    const float4 av = __ldg(&arow[sp * MULc + u]);
                    const float4* wv = reinterpret_cast<const float4*>(wbase + pp * 16);
                    acc = f4fma(av.x, wv[0], acc);
                    acc = f4fma(av.y, wv[1], acc);
                    acc = f4fma(av.z, wv[2], acc);
                    acc = f4fma(av.w, wv[3], acc);
                }
            }
            orow[z * MULc + u] = acc;
        }
    }
}

extern "C" void kernel_launch(void* const* d_in, const int* in_sizes, int n_in,
                              void* d_out, int out_size) {
    const float* x0 = (const float*)d_in[0];
    const int*   i0 = (const int*)d_in[1];
    const float* x1 = (const float*)d_in[2];
    const float* C3 = (const float*)d_in[3];
    const float* C4 = (const float*)d_in[4];
    const int*   p3 = (const int*)d_in[5];
    const int*   p4 = (const int*)d_in[6];

    const int E = in_sizes[1];
    const int blocks = (E + EPB - 1) / EPB;
    tp_kernel<<<blocks, NTHREADS>>>(x0, i0, x1, C3, C4, p3, p4, (float*)d_out, E);
}

// round 14
// speedup vs baseline: 2.8535x; 2.8535x over previous
#include <cuda_runtime.h>

#define MULc 16
#define S0c 8
#define S1c 8
#define SOUTc 8
#define P3c 8
#define P4c 4
#define NPATH (P3c + P4c)

#define EPB 8
#define NTHREADS 128
#define WS 196                          // == 4 (mod 32): edge rows tile banks conflict-free

__device__ __forceinline__ float4 f4fma(float s, float4 v, float4 a) {
    a.x = fmaf(s, v.x, a.x);
    a.y = fmaf(s, v.y, a.y);
    a.z = fmaf(s, v.z, a.z);
    a.w = fmaf(s, v.w, a.w);
    return a;
}

__global__ __launch_bounds__(NTHREADS, 10) void tp_kernel(
    const float* __restrict__ x0, const int* __restrict__ i0,
    const float* __restrict__ x1, const float* __restrict__ C3,
    const float* __restrict__ C4, const int* __restrict__ p3,
    const int* __restrict__ p4, float* __restrict__ out, int E)
{
    __shared__ __align__(16) float  sW[EPB * WS];     // 6272 B
    __shared__ __align__(16) float4 sx1[EPB * S1c];   // 1024 B

    const int tid  = threadIdx.x;
    const int base = blockIdx.x * EPB;
    int nE = E - base; if (nE > EPB) nE = EPB;

    // ---- stage x1 rows (8 edges x 8 float4 = 64 entries) ----
    if (tid < nE * 8)
        sx1[tid] = reinterpret_cast<const float4*>(x1 + (size_t)base * 32)[tid];
    __syncthreads();

    // ---- W build: 4 warps, C in registers, amortized over 8 edges ----
    {
        const int warp = tid >> 5, lane = tid & 31;
        const int g  = (lane >> 4) & 1;    // half-warp
        const int l  = lane & 15;          // (i,k)
        const int wi = l >> 2, wk = l & 3;

        // 3-paths: p = 2*warp + g  (covers 0..7), all edges
        {
            const int p = warp * 2 + g;
            const int segb = __ldg(&p3[p * 3 + 1]);
            const float c0  = __ldg(&C3[p * 64 + wi * 16 + 0  + wk]);
            const float c1  = __ldg(&C3[p * 64 + wi * 16 + 4  + wk]);
            const float c2  = __ldg(&C3[p * 64 + wi * 16 + 8  + wk]);
            const float c3v = __ldg(&C3[p * 64 + wi * 16 + 12 + wk]);
            for (int e = 0; e < nE; e++) {
                const float4 b = sx1[e * S1c + segb];
                sW[e * WS + p * 16 + l] =
                    fmaf(b.x, c0, fmaf(b.y, c1, fmaf(b.z, c2, b.w * c3v)));
            }
        }
        // 4-paths: q = warp, edges split by half-warp
        {
            const int q = warp;
            const int segb = __ldg(&p4[q * 4 + 1]);
            const int segc = __ldg(&p4[q * 4 + 2]);
            float creg[16];
            #pragma unroll
            for (int j = 0; j < 4; j++)
                #pragma unroll
                for (int m = 0; m < 4; m++)
                    creg[j * 4 + m] = __ldg(&C4[q * 256 + wi * 64 + j * 16 + m * 4 + wk]);
            const int e0 = g * (EPB / 2);
            int e1 = e0 + (EPB / 2); if (e1 > nE) e1 = nE;
            for (int e = e0; e < e1; e++) {
                const float4 b = sx1[e * S1c + segb];
                const float4 c = sx1[e * S1c + segc];
                float t0 = fmaf(c.x, creg[0],  fmaf(c.y, creg[1],  fmaf(c.z, creg[2],  c.w * creg[3])));
                float t1 = fmaf(c.x, creg[4],  fmaf(c.y, creg[5],  fmaf(c.z, creg[6],  c.w * creg[7])));
                float t2 = fmaf(c.x, creg[8],  fmaf(c.y, creg[9],  fmaf(c.z, creg[10], c.w * creg[11])));
                float t3 = fmaf(c.x, creg[12], fmaf(c.y, creg[13], fmaf(c.z, creg[14], c.w * creg[15])));
                sW[e * WS + (P3c + q) * 16 + l] =
                    fmaf(b.x, t0, fmaf(b.y, t1, fmaf(b.z, t2, b.w * t3)));
            }
        }
    }
    __syncthreads();

    // ---- contrib: 16 lanes per edge, lane = mul index; block covers all 8 edges ----
    const int eL = tid >> 4;       // edge slot 0..7
    const int u  = tid & 15;       // mul index
    const int e  = base + eL;
    if (e >= E) return;

    // packed metadata: s | (z << 16)
    int m3[P3c], m4[P4c];
    #pragma unroll
    for (int p = 0; p < P3c; p++)
        m3[p] = __ldg(&p3[p * 3 + 0]) | (__ldg(&p3[p * 3 + 2]) << 16);
    #pragma unroll
    for (int p = 0; p < P4c; p++)
        m4[p] = __ldg(&p4[p * 4 + 0]) | (__ldg(&p4[p * 4 + 3]) << 16);

    const float4* arow = reinterpret_cast<const float4*>(
        x0 + (size_t)__ldg(&i0[e]) * (S0c * MULc * 4));
    float4* orow = reinterpret_cast<float4*>(out + (size_t)e * (SOUTc * MULc * 4));
    const float* wbase = sW + eL * WS;

    #pragma unroll
    for (int z = 0; z < SOUTc; z++) {
        float4 acc = make_float4(0.f, 0.f, 0.f, 0.f);
        #pragma unroll
        for (int pp = 0; pp < NPATH; pp++) {
            const int meta = (pp < P3c) ? m3[pp] : m4[pp - P3c];
            if ((meta >> 16) == z) {
                const int sp = meta & 0xffff;
                const float4 av = __ldg(&arow[sp * MULc + u]);
                const float4* wv = reinterpret_cast<const float4*>(wbase + pp * 16);
                acc = f4fma(av.x, wv[0], acc);
                acc = f4fma(av.y, wv[1], acc);
                acc = f4fma(av.z, wv[2], acc);
                acc = f4fma(av.w, wv[3], acc);
            }
        }
        __stcs(&orow[z * MULc + u], acc);   // streaming store: don't evict x0 from L2
    }
}

extern "C" void kernel_launch(void* const* d_in, const int* in_sizes, int n_in,
                              void* d_out, int out_size) {
    const float* x0 = (const float*)d_in[0];
    const int*   i0 = (const int*)d_in[1];
    const float* x1 = (const float*)d_in[2];
    const float* C3 = (const float*)d_in[3];
    const float* C4 = (const float*)d_in[4];
    const int*   p3 = (const int*)d_in[5];
    const int*   p4 = (const int*)d_in[6];

    const int E = in_sizes[1];
    const int blocks = (E + EPB - 1) / EPB;
    tp_kernel<<<blocks, NTHREADS>>>(x0, i0, x1, C3, C4, p3, p4, (float*)d_out, E);
}

// round 15
// speedup vs baseline: 3.4337x; 1.2034x over previous
#include <cuda_runtime.h>

#define MULc 16
#define S0c 8
#define S1c 8
#define SOUTc 8
#define P3c 8
#define P4c 4
#define NPATH (P3c + P4c)

#define EPB 16
#define NTHREADS 128
#define WS 196                          // == 4 (mod 32): edge rows tile banks conflict-free

__device__ __forceinline__ float4 f4fma(float s, float4 v, float4 a) {
    a.x = fmaf(s, v.x, a.x);
    a.y = fmaf(s, v.y, a.y);
    a.z = fmaf(s, v.z, a.z);
    a.w = fmaf(s, v.w, a.w);
    return a;
}

__global__ __launch_bounds__(NTHREADS, 9) void tp_kernel(
    const float* __restrict__ x0, const int* __restrict__ i0,
    const float* __restrict__ x1, const float* __restrict__ C3,
    const float* __restrict__ C4, const int* __restrict__ p3,
    const int* __restrict__ p4, float* __restrict__ out, int E)
{
    __shared__ __align__(16) float  sW[EPB * WS];     // 12544 B
    __shared__ __align__(16) float4 sx1[EPB * S1c];   // 2048 B

    const int tid  = threadIdx.x;
    const int base = blockIdx.x * EPB;
    int nE = E - base; if (nE > EPB) nE = EPB;

    // ---- stage x1 rows (16 edges x 8 float4 = 128: one per thread) ----
    if (tid < nE * 8)
        sx1[tid] = reinterpret_cast<const float4*>(x1 + (size_t)base * 32)[tid];
    __syncthreads();

    // ---- W build: 4 warps, C in registers, amortized over 16 edges ----
    {
        const int warp = tid >> 5, lane = tid & 31;
        const int g  = (lane >> 4) & 1;    // half-warp
        const int l  = lane & 15;          // (i,k)
        const int wi = l >> 2, wk = l & 3;

        // 3-paths: p = 2*warp + g  (covers 0..7), all 16 edges
        {
            const int p = warp * 2 + g;
            const int segb = __ldg(&p3[p * 3 + 1]);
            const float c0  = __ldg(&C3[p * 64 + wi * 16 + 0  + wk]);
            const float c1  = __ldg(&C3[p * 64 + wi * 16 + 4  + wk]);
            const float c2  = __ldg(&C3[p * 64 + wi * 16 + 8  + wk]);
            const float c3v = __ldg(&C3[p * 64 + wi * 16 + 12 + wk]);
            for (int e = 0; e < nE; e++) {
                const float4 b = sx1[e * S1c + segb];
                sW[e * WS + p * 16 + l] =
                    fmaf(b.x, c0, fmaf(b.y, c1, fmaf(b.z, c2, b.w * c3v)));
            }
        }
        // 4-paths: q = warp, edges split by half-warp (8 each)
        {
            const int q = warp;
            const int segb = __ldg(&p4[q * 4 + 1]);
            const int segc = __ldg(&p4[q * 4 + 2]);
            float creg[16];
            #pragma unroll
            for (int j = 0; j < 4; j++)
                #pragma unroll
                for (int m = 0; m < 4; m++)
                    creg[j * 4 + m] = __ldg(&C4[q * 256 + wi * 64 + j * 16 + m * 4 + wk]);
            const int e0 = g * (EPB / 2);
            int e1 = e0 + (EPB / 2); if (e1 > nE) e1 = nE;
            for (int e = e0; e < e1; e++) {
                const float4 b = sx1[e * S1c + segb];
                const float4 c = sx1[e * S1c + segc];
                float t0 = fmaf(c.x, creg[0],  fmaf(c.y, creg[1],  fmaf(c.z, creg[2],  c.w * creg[3])));
                float t1 = fmaf(c.x, creg[4],  fmaf(c.y, creg[5],  fmaf(c.z, creg[6],  c.w * creg[7])));
                float t2 = fmaf(c.x, creg[8],  fmaf(c.y, creg[9],  fmaf(c.z, creg[10], c.w * creg[11])));
                float t3 = fmaf(c.x, creg[12], fmaf(c.y, creg[13], fmaf(c.z, creg[14], c.w * creg[15])));
                sW[e * WS + (P3c + q) * 16 + l] =
                    fmaf(b.x, t0, fmaf(b.y, t1, fmaf(b.z, t2, b.w * t3)));
            }
        }
    }
    __syncthreads();

    // ---- contrib: 8 lanes per edge, 2 muls per thread (u0, u0+8) ----
    const int eL = tid >> 3;       // edge slot 0..15
    const int u0 = tid & 7;        // first mul index
    const int e  = base + eL;
    if (e >= E) return;

    // packed metadata: s | (z << 16)
    int m3[P3c], m4[P4c];
    #pragma unroll
    for (int p = 0; p < P3c; p++)
        m3[p] = __ldg(&p3[p * 3 + 0]) | (__ldg(&p3[p * 3 + 2]) << 16);
    #pragma unroll
    for (int p = 0; p < P4c; p++)
        m4[p] = __ldg(&p4[p * 4 + 0]) | (__ldg(&p4[p * 4 + 3]) << 16);

    const float4* arow = reinterpret_cast<const float4*>(
        x0 + (size_t)__ldg(&i0[e]) * (S0c * MULc * 4));
    float4* orow = reinterpret_cast<float4*>(out + (size_t)e * (SOUTc * MULc * 4));
    const float* wbase = sW + eL * WS;

    #pragma unroll
    for (int z = 0; z < SOUTc; z++) {
        float4 acc0 = make_float4(0.f, 0.f, 0.f, 0.f);
        float4 acc1 = acc0;
        #pragma unroll
        for (int pp = 0; pp < NPATH; pp++) {
            const int meta = (pp < P3c) ? m3[pp] : m4[pp - P3c];
            if ((meta >> 16) == z) {
                const int sp = meta & 0xffff;
                const float4 av0 = __ldg(&arow[sp * MULc + u0]);
                const float4 av1 = __ldg(&arow[sp * MULc + u0 + 8]);
                const float4* wv = reinterpret_cast<const float4*>(wbase + pp * 16);
                const float4 W0 = wv[0], W1 = wv[1], W2 = wv[2], W3 = wv[3];
                acc0 = f4fma(av0.x, W0, acc0);
                acc0 = f4fma(av0.y, W1, acc0);
                acc0 = f4fma(av0.z, W2, acc0);
                acc0 = f4fma(av0.w, W3, acc0);
                acc1 = f4fma(av1.x, W0, acc1);
                acc1 = f4fma(av1.y, W1, acc1);
                acc1 = f4fma(av1.z, W2, acc1);
                acc1 = f4fma(av1.w, W3, acc1);
            }
        }
        __stcs(&orow[z * MULc + u0], acc0);
        __stcs(&orow[z * MULc + u0 + 8], acc1);
    }
}

extern "C" void kernel_launch(void* const* d_in, const int* in_sizes, int n_in,
                              void* d_out, int out_size) {
    const float* x0 = (const float*)d_in[0];
    const int*   i0 = (const int*)d_in[1];
    const float* x1 = (const float*)d_in[2];
    const float* C3 = (const float*)d_in[3];
    const float* C4 = (const float*)d_in[4];
    const int*   p3 = (const int*)d_in[5];
    const int*   p4 = (const int*)d_in[6];

    const int E = in_sizes[1];
    const int blocks = (E + EPB - 1) / EPB;
    tp_kernel<<<blocks, NTHREADS>>>(x0, i0, x1, C3, C4, p3, p4, (float*)d_out, E);
}

// round 16
// speedup vs baseline: 4.3942x; 1.2797x over previous
#include <cuda_runtime.h>

#define MULc 16
#define S0c 8
#define S1c 8
#define SOUTc 8
#define P3c 8
#define P4c 4
#define NPATH (P3c + P4c)

#define EPB 16
#define NTHREADS 128
#define WS 196                          // == 4 (mod 32): edge rows tile banks conflict-free

// sorted path metadata: [0..11] = s | (z<<8) | (Wslot<<16), [12] = zmask
__device__ int g_meta[13];

__device__ __forceinline__ float4 f4fma(float s, float4 v, float4 a) {
    a.x = fmaf(s, v.x, a.x);
    a.y = fmaf(s, v.y, a.y);
    a.z = fmaf(s, v.z, a.z);
    a.w = fmaf(s, v.w, a.w);
    return a;
}

__global__ void setup_kernel(const int* __restrict__ p3, const int* __restrict__ p4) {
    if (threadIdx.x != 0) return;
    int meta[NPATH];
    #pragma unroll
    for (int p = 0; p < P3c; p++)
        meta[p] = p3[p * 3 + 0] | (p3[p * 3 + 2] << 8) | (p << 16);
    #pragma unroll
    for (int q = 0; q < P4c; q++)
        meta[P3c + q] = p4[q * 4 + 0] | (p4[q * 4 + 3] << 8) | ((P3c + q) << 16);
    // insertion sort by z
    for (int i = 1; i < NPATH; i++) {
        int key = meta[i], kz = (key >> 8) & 0xff;
        int j = i - 1;
        while (j >= 0 && ((meta[j] >> 8) & 0xff) > kz) { meta[j + 1] = meta[j]; j--; }
        meta[j + 1] = key;
    }
    int zmask = 0;
    for (int i = 0; i < NPATH; i++) zmask |= 1 << ((meta[i] >> 8) & 0xff);
    for (int i = 0; i < NPATH; i++) g_meta[i] = meta[i];
    g_meta[NPATH] = zmask;
}

__global__ __launch_bounds__(NTHREADS, 9) void tp_kernel(
    const float* __restrict__ x0, const int* __restrict__ i0,
    const float* __restrict__ x1, const float* __restrict__ C3,
    const float* __restrict__ C4, const int* __restrict__ p3,
    const int* __restrict__ p4, float* __restrict__ out, int E)
{
    __shared__ __align__(16) float  sW[EPB * WS];     // 12544 B
    __shared__ __align__(16) float4 sx1[EPB * S1c];   // 2048 B

    const int tid  = threadIdx.x;
    const int base = blockIdx.x * EPB;
    int nE = E - base; if (nE > EPB) nE = EPB;

    // ---- stage x1 rows (16 edges x 8 float4 = 128: one per thread) ----
    if (tid < nE * 8)
        sx1[tid] = reinterpret_cast<const float4*>(x1 + (size_t)base * 32)[tid];
    __syncthreads();

    // ---- W build: 4 warps, C in registers, amortized over 16 edges ----
    {
        const int warp = tid >> 5, lane = tid & 31;
        const int g  = (lane >> 4) & 1;    // half-warp
        const int l  = lane & 15;          // (i,k)
        const int wi = l >> 2, wk = l & 3;

        // 3-paths: p = 2*warp + g, all 16 edges (W slot = p)
        {
            const int p = warp * 2 + g;
            const int segb = __ldg(&p3[p * 3 + 1]);
            const float c0  = __ldg(&C3[p * 64 + wi * 16 + 0  + wk]);
            const float c1  = __ldg(&C3[p * 64 + wi * 16 + 4  + wk]);
            const float c2  = __ldg(&C3[p * 64 + wi * 16 + 8  + wk]);
            const float c3v = __ldg(&C3[p * 64 + wi * 16 + 12 + wk]);
            for (int e = 0; e < nE; e++) {
                const float4 b = sx1[e * S1c + segb];
                sW[e * WS + p * 16 + l] =
                    fmaf(b.x, c0, fmaf(b.y, c1, fmaf(b.z, c2, b.w * c3v)));
            }
        }
        // 4-paths: q = warp, edges split by half-warp (W slot = 8 + q)
        {
            const int q = warp;
            const int segb = __ldg(&p4[q * 4 + 1]);
            const int segc = __ldg(&p4[q * 4 + 2]);
            float creg[16];
            #pragma unroll
            for (int j = 0; j < 4; j++)
                #pragma unroll
                for (int m = 0; m < 4; m++)
                    creg[j * 4 + m] = __ldg(&C4[q * 256 + wi * 64 + j * 16 + m * 4 + wk]);
            const int e0 = g * (EPB / 2);
            int e1 = e0 + (EPB / 2); if (e1 > nE) e1 = nE;
            for (int e = e0; e < e1; e++) {
                const float4 b = sx1[e * S1c + segb];
                const float4 c = sx1[e * S1c + segc];
                float t0 = fmaf(c.x, creg[0],  fmaf(c.y, creg[1],  fmaf(c.z, creg[2],  c.w * creg[3])));
                float t1 = fmaf(c.x, creg[4],  fmaf(c.y, creg[5],  fmaf(c.z, creg[6],  c.w * creg[7])));
                float t2 = fmaf(c.x, creg[8],  fmaf(c.y, creg[9],  fmaf(c.z, creg[10], c.w * creg[11])));
                float t3 = fmaf(c.x, creg[12], fmaf(c.y, creg[13], fmaf(c.z, creg[14], c.w * creg[15])));
                sW[e * WS + (P3c + q) * 16 + l] =
                    fmaf(b.x, t0, fmaf(b.y, t1, fmaf(b.z, t2, b.w * t3)));
            }
        }
    }
    __syncthreads();

    // ---- contrib: 8 lanes per edge, 2 muls per thread; z-sorted flat path loop ----
    const int eL = tid >> 3;       // edge slot 0..15
    const int u0 = tid & 7;        // first mul index
    const int e  = base + eL;
    if (e >= E) return;

    const float4* arow = reinterpret_cast<const float4*>(
        x0 + (size_t)__ldg(&i0[e]) * (S0c * MULc * 4));
    float4* orow = reinterpret_cast<float4*>(out + (size_t)e * (SOUTc * MULc * 4));
    const float* wbase = sW + eL * WS;

    const float4 zero4 = make_float4(0.f, 0.f, 0.f, 0.f);
    float4 acc0 = zero4, acc1 = zero4;
    int zcur = (__ldg(&g_meta[0]) >> 8) & 0xff;

    #pragma unroll
    for (int pp = 0; pp < NPATH; pp++) {
        const int meta = __ldg(&g_meta[pp]);
        const int sp   = meta & 0xff;
        const int zp   = (meta >> 8) & 0xff;
        const int slot = meta >> 16;

        if (zp != zcur) {                        // uniform flush on z change
            __stcs(&orow[zcur * MULc + u0], acc0);
            __stcs(&orow[zcur * MULc + u0 + 8], acc1);
            acc0 = zero4; acc1 = zero4;
            zcur = zp;
        }

        const float4 av0 = __ldg(&arow[sp * MULc + u0]);
        const float4 av1 = __ldg(&arow[sp * MULc + u0 + 8]);
        const float4* wv = reinterpret_cast<const float4*>(wbase + slot * 16);
        const float4 W0 = wv[0], W1 = wv[1], W2 = wv[2], W3 = wv[3];
        acc0 = f4fma(av0.x, W0, acc0);
        acc0 = f4fma(av0.y, W1, acc0);
        acc0 = f4fma(av0.z, W2, acc0);
        acc0 = f4fma(av0.w, W3, acc0);
        acc1 = f4fma(av1.x, W0, acc1);
        acc1 = f4fma(av1.y, W1, acc1);
        acc1 = f4fma(av1.z, W2, acc1);
        acc1 = f4fma(av1.w, W3, acc1);
    }
    // final flush
    __stcs(&orow[zcur * MULc + u0], acc0);
    __stcs(&orow[zcur * MULc + u0 + 8], acc1);

    // zero-fill output segments with no contributing paths
    const int zmask = __ldg(&g_meta[NPATH]);
    #pragma unroll
    for (int z = 0; z < SOUTc; z++) {
        if (!((zmask >> z) & 1)) {
            __stcs(&orow[z * MULc + u0], zero4);
            __stcs(&orow[z * MULc + u0 + 8], zero4);
        }
    }
}

extern "C" void kernel_launch(void* const* d_in, const int* in_sizes, int n_in,
                              void* d_out, int out_size) {
    const float* x0 = (const float*)d_in[0];
    const int*   i0 = (const int*)d_in[1];
    const float* x1 = (const float*)d_in[2];
    const float* C3 = (const float*)d_in[3];
    const float* C4 = (const float*)d_in[4];
    const int*   p3 = (const int*)d_in[5];
    const int*   p4 = (const int*)d_in[6];

    const int E = in_sizes[1];
    setup_kernel<<<1, 32>>>(p3, p4);
    const int blocks = (E + EPB - 1) / EPB;
    tp_kernel<<<blocks, NTHREADS>>>(x0, i0, x1, C3, C4, p3, p4, (float*)d_out, E);
}